// round 2
// baseline (speedup 1.0000x reference)
#include <cuda_runtime.h>
#include <cuda_bf16.h>
#include <math.h>

#define NN 100000
#define FIN 50
#define CC 32

// Scratch (no allocations allowed)
__device__ float g_agg1[NN * FIN];   // layer-1 aggregation buffer (50-wide)
__device__ float g_h[NN * CC];       // hidden activations (in-place across layers)
__device__ float g_agg[NN * CC];     // layer-2/3 aggregation buffer (32-wide)

__device__ __forceinline__ void atomicMaxF(float* addr, float v) {
    v = v + 0.0f;  // canonicalize -0.0 -> +0.0
    if (v >= 0.0f) {
        atomicMax((int*)addr, __float_as_int(v));
    } else {
        atomicMin((unsigned int*)addr, __float_as_uint(v));
    }
}

// ---------------- init to -inf (writes globals directly) ----------------
__global__ void init1_neg_inf(int n) {
    int i = blockIdx.x * blockDim.x + threadIdx.x;
    if (i < n) g_agg1[i] = __int_as_float(0xFF800000);
}
__global__ void init2_neg_inf(int n) {
    int i = blockIdx.x * blockDim.x + threadIdx.x;
    if (i < n) g_agg[i] = __int_as_float(0xFF800000);
}

// ---------------- scatter max, d=50 (layer 1, reads x) ----------------
__global__ void scatter_max50(const float* __restrict__ x,
                              const int* __restrict__ ei, int E) {
    int idx = blockIdx.x * blockDim.x + threadIdx.x;
    int total = E * FIN;
    if (idx >= total) return;
    int e = idx / FIN;
    int c = idx - e * FIN;
    int s = ei[e];
    int d = ei[E + e];
    atomicMaxF(&g_agg1[d * FIN + c], x[s * FIN + c]);
}

// ---------------- scatter max, d=32 (layers 2,3, reads g_h) ----------------
__global__ void scatter_max32(const int* __restrict__ ei, int E) {
    int idx = blockIdx.x * blockDim.x + threadIdx.x;
    int total = E << 5;
    if (idx >= total) return;
    int e = idx >> 5;
    int c = idx & 31;
    int s = ei[e];
    int d = ei[E + e];
    atomicMaxF(&g_agg[d * CC + c], g_h[s * CC + c]);
}

// ---------------- layer 1 finalize: h = relu(agg1 @ Wl + bl + x @ Wr) ----------------
// one warp per node; lane = output channel
__global__ void finalize1(const float* __restrict__ x,
                          const float* __restrict__ Wl,
                          const float* __restrict__ bl,
                          const float* __restrict__ Wr,
                          int n_nodes) {
    __shared__ float sWl[FIN * CC];
    __shared__ float sWr[FIN * CC];
    __shared__ float sbl[CC];
    __shared__ float sA[8][FIN];
    __shared__ float sX[8][FIN];

    for (int i = threadIdx.x; i < FIN * CC; i += blockDim.x) {
        sWl[i] = Wl[i];
        sWr[i] = Wr[i];
    }
    if (threadIdx.x < CC) sbl[threadIdx.x] = bl[threadIdx.x];
    __syncthreads();

    int gw = (blockIdx.x * blockDim.x + threadIdx.x) >> 5;
    int lane = threadIdx.x & 31;
    int wl = threadIdx.x >> 5;
    if (gw >= n_nodes) return;

    for (int k = lane; k < FIN; k += 32) {
        float a = g_agg1[gw * FIN + k];
        sA[wl][k] = isfinite(a) ? a : 0.0f;
        sX[wl][k] = x[gw * FIN + k];
    }
    __syncwarp();

    float acc = sbl[lane];
#pragma unroll
    for (int k = 0; k < FIN; k++) {
        acc += sA[wl][k] * sWl[k * CC + lane] + sX[wl][k] * sWr[k * CC + lane];
    }
    acc = fmaxf(acc, 0.0f);
    g_h[gw * CC + lane] = acc;
}

// ---------------- layer 2 finalize: h = relu(agg @ Wl + bl + h @ Wr) (in-place h) ----------------
__global__ void finalize2(const float* __restrict__ Wl,
                          const float* __restrict__ bl,
                          const float* __restrict__ Wr,
                          int n_nodes) {
    __shared__ float sWl[CC * CC];
    __shared__ float sWr[CC * CC];
    __shared__ float sbl[CC];
    for (int i = threadIdx.x; i < CC * CC; i += blockDim.x) {
        sWl[i] = Wl[i];
        sWr[i] = Wr[i];
    }
    if (threadIdx.x < CC) sbl[threadIdx.x] = bl[threadIdx.x];
    __syncthreads();

    int gw = (blockIdx.x * blockDim.x + threadIdx.x) >> 5;
    int lane = threadIdx.x & 31;
    if (gw >= n_nodes) return;

    float a_l = g_agg[gw * CC + lane];
    a_l = isfinite(a_l) ? a_l : 0.0f;
    float x_l = g_h[gw * CC + lane];

    float acc = sbl[lane];
#pragma unroll
    for (int k = 0; k < CC; k++) {
        float a = __shfl_sync(0xffffffff, a_l, k);
        float xv = __shfl_sync(0xffffffff, x_l, k);
        acc += a * sWl[k * CC + lane] + xv * sWr[k * CC + lane];
    }
    acc = fmaxf(acc, 0.0f);
    g_h[gw * CC + lane] = acc;
}

// ---------------- layer 3 finalize + log_softmax -> out ----------------
__global__ void finalize3(const float* __restrict__ Wl,
                          const float* __restrict__ bl,
                          const float* __restrict__ Wr,
                          float* __restrict__ out, int n_nodes) {
    __shared__ float sWl[CC * CC];
    __shared__ float sWr[CC * CC];
    __shared__ float sbl[CC];
    for (int i = threadIdx.x; i < CC * CC; i += blockDim.x) {
        sWl[i] = Wl[i];
        sWr[i] = Wr[i];
    }
    if (threadIdx.x < CC) sbl[threadIdx.x] = bl[threadIdx.x];
    __syncthreads();

    int gw = (blockIdx.x * blockDim.x + threadIdx.x) >> 5;
    int lane = threadIdx.x & 31;
    if (gw >= n_nodes) return;

    float a_l = g_agg[gw * CC + lane];
    a_l = isfinite(a_l) ? a_l : 0.0f;
    float x_l = g_h[gw * CC + lane];

    float acc = sbl[lane];
#pragma unroll
    for (int k = 0; k < CC; k++) {
        float a = __shfl_sync(0xffffffff, a_l, k);
        float xv = __shfl_sync(0xffffffff, x_l, k);
        acc += a * sWl[k * CC + lane] + xv * sWr[k * CC + lane];
    }

    // log_softmax over 32 channels (full warp)
    float m = acc;
#pragma unroll
    for (int o = 16; o > 0; o >>= 1) m = fmaxf(m, __shfl_xor_sync(0xffffffff, m, o));
    float e = expf(acc - m);
    float s = e;
#pragma unroll
    for (int o = 16; o > 0; o >>= 1) s += __shfl_xor_sync(0xffffffff, s, o);
    out[gw * CC + lane] = acc - m - logf(s);
}

extern "C" void kernel_launch(void* const* d_in, const int* in_sizes, int n_in,
                              void* d_out, int out_size) {
    const float* x = (const float*)d_in[0];
    const int* ei = (const int*)d_in[1];   // int32: JAX x64 disabled
    const float* Wl1 = (const float*)d_in[2];
    const float* bl1 = (const float*)d_in[3];
    const float* Wr1 = (const float*)d_in[4];
    const float* Wl2 = (const float*)d_in[5];
    const float* bl2 = (const float*)d_in[6];
    const float* Wr2 = (const float*)d_in[7];
    const float* Wl3 = (const float*)d_in[8];
    const float* bl3 = (const float*)d_in[9];
    const float* Wr3 = (const float*)d_in[10];
    float* out = (float*)d_out;

    int N = in_sizes[0] / FIN;     // 100000
    int E = in_sizes[1] / 2;       // 1600000

    const int TB = 256;
    int warps_per_blk = TB / 32;
    int node_blocks = (N + warps_per_blk - 1) / warps_per_blk;

    // ---- layer 1 ----
    {
        int n = N * FIN;
        init1_neg_inf<<<(n + TB - 1) / TB, TB>>>(n);
        int tot = E * FIN;
        scatter_max50<<<(tot + TB - 1) / TB, TB>>>(x, ei, E);
        finalize1<<<node_blocks, TB>>>(x, Wl1, bl1, Wr1, N);
    }
    // ---- layer 2 ----
    {
        int n = N * CC;
        init2_neg_inf<<<(n + TB - 1) / TB, TB>>>(n);
        int tot = E * CC;
        scatter_max32<<<(tot + TB - 1) / TB, TB>>>(ei, E);
        finalize2<<<node_blocks, TB>>>(Wl2, bl2, Wr2, N);
    }
    // ---- layer 3 ----
    {
        int n = N * CC;
        init2_neg_inf<<<(n + TB - 1) / TB, TB>>>(n);
        int tot = E * CC;
        scatter_max32<<<(tot + TB - 1) / TB, TB>>>(ei, E);
        finalize3<<<node_blocks, TB>>>(Wl3, bl3, Wr3, out, N);
    }
}

// round 3
// speedup vs baseline: 2.3274x; 2.3274x over previous
#include <cuda_runtime.h>
#include <cuda_bf16.h>
#include <math.h>
#include <float.h>

#define NN 100000
#define EE 1600000
#define FIN 50
#define CC 32
#define SCAN_B 1024

// ---------------- scratch (__device__ globals; no allocation) ----------------
__device__ int g_cnt[NN];        // per-dst degree
__device__ int g_scan[NN];       // per-block inclusive scan of cnt
__device__ int g_bsum[128];      // block sums
__device__ int g_boff[128];      // exclusive-scanned block sums
__device__ int g_rowptr[NN + 1]; // CSR row pointer
__device__ int g_cursor[NN];     // fill cursor
__device__ int g_adj[EE];        // src indices grouped by dst
__device__ float g_ha[NN * CC];  // layer-1 output
__device__ float g_hb[NN * CC];  // layer-2 output

// ---------------- CSR build ----------------
__global__ void zero_cnt() {
    int i = blockIdx.x * blockDim.x + threadIdx.x;
    if (i < NN) g_cnt[i] = 0;
}

__global__ void hist_dst(const int* __restrict__ ei, int E) {
    int e = blockIdx.x * blockDim.x + threadIdx.x;
    if (e < E) atomicAdd(&g_cnt[ei[E + e]], 1);
}

// per-block inclusive scan (1024 threads)
__global__ void scan_blocks() {
    __shared__ int s[SCAN_B];
    int i = blockIdx.x * SCAN_B + threadIdx.x;
    int v = (i < NN) ? g_cnt[i] : 0;
    s[threadIdx.x] = v;
    __syncthreads();
#pragma unroll
    for (int off = 1; off < SCAN_B; off <<= 1) {
        int t = (threadIdx.x >= off) ? s[threadIdx.x - off] : 0;
        __syncthreads();
        s[threadIdx.x] += t;
        __syncthreads();
    }
    if (i < NN) g_scan[i] = s[threadIdx.x];
    if (threadIdx.x == SCAN_B - 1) g_bsum[blockIdx.x] = s[SCAN_B - 1];
}

// exclusive scan of block sums (single block, 128 threads; nb <= 128)
__global__ void scan_bsums(int nb) {
    __shared__ int s[128];
    int t = threadIdx.x;
    int v = (t < nb) ? g_bsum[t] : 0;
    s[t] = v;
    __syncthreads();
#pragma unroll
    for (int off = 1; off < 128; off <<= 1) {
        int u = (t >= off) ? s[t - off] : 0;
        __syncthreads();
        s[t] += u;
        __syncthreads();
    }
    if (t < nb) g_boff[t] = s[t] - v;  // exclusive
}

__global__ void make_rowptr(int E) {
    int i = blockIdx.x * blockDim.x + threadIdx.x;
    if (i < NN) {
        int excl = g_scan[i] - g_cnt[i] + g_boff[i / SCAN_B];
        g_rowptr[i] = excl;
        g_cursor[i] = excl;
    }
    if (i == 0) g_rowptr[NN] = E;
}

__global__ void csr_scatter(const int* __restrict__ ei, int E) {
    int e = blockIdx.x * blockDim.x + threadIdx.x;
    if (e >= E) return;
    int s = ei[e];
    int d = ei[E + e];
    int pos = atomicAdd(&g_cursor[d], 1);
    g_adj[pos] = s;
}

// ---------------- layer 1: gather-max(d=50) + GEMV + relu ----------------
__global__ void layer1(const float* __restrict__ x,
                       const float* __restrict__ Wl,
                       const float* __restrict__ bl,
                       const float* __restrict__ Wr) {
    __shared__ float sWl[FIN * CC];
    __shared__ float sWr[FIN * CC];
    __shared__ float sbl[CC];
    for (int i = threadIdx.x; i < FIN * CC; i += blockDim.x) {
        sWl[i] = Wl[i];
        sWr[i] = Wr[i];
    }
    if (threadIdx.x < CC) sbl[threadIdx.x] = bl[threadIdx.x];
    __syncthreads();

    int node = (blockIdx.x * blockDim.x + threadIdx.x) >> 5;
    int lane = threadIdx.x & 31;
    if (node >= NN) return;

    int beg = g_rowptr[node];
    int end = g_rowptr[node + 1];
    int c1 = 32 + lane;
    bool has1 = c1 < FIN;

    float m0 = -FLT_MAX, m1 = -FLT_MAX;
    for (int p = beg; p < end; ++p) {
        int s = g_adj[p];
        const float* xs = x + s * FIN;
        m0 = fmaxf(m0, xs[lane]);
        if (has1) m1 = fmaxf(m1, xs[c1]);
    }
    if (beg == end) { m0 = 0.0f; m1 = 0.0f; }

    const float* xn = x + node * FIN;
    float x0 = xn[lane];
    float x1 = has1 ? xn[c1] : 0.0f;

    float acc = sbl[lane];
#pragma unroll
    for (int k = 0; k < FIN; k++) {
        float a, xv;
        if (k < 32) {
            a = __shfl_sync(0xffffffff, m0, k);
            xv = __shfl_sync(0xffffffff, x0, k);
        } else {
            a = __shfl_sync(0xffffffff, m1, k - 32);
            xv = __shfl_sync(0xffffffff, x1, k - 32);
        }
        acc += a * sWl[k * CC + lane] + xv * sWr[k * CC + lane];
    }
    g_ha[node * CC + lane] = fmaxf(acc, 0.0f);
}

// ---------------- layers 2/3: gather-max(d=32) + GEMV (+relu | +log_softmax) --
template <bool FINAL>
__global__ void layer23(const float* __restrict__ hin,
                        float* __restrict__ hout,
                        const float* __restrict__ Wl,
                        const float* __restrict__ bl,
                        const float* __restrict__ Wr) {
    __shared__ float sWl[CC * CC];
    __shared__ float sWr[CC * CC];
    __shared__ float sbl[CC];
    for (int i = threadIdx.x; i < CC * CC; i += blockDim.x) {
        sWl[i] = Wl[i];
        sWr[i] = Wr[i];
    }
    if (threadIdx.x < CC) sbl[threadIdx.x] = bl[threadIdx.x];
    __syncthreads();

    int node = (blockIdx.x * blockDim.x + threadIdx.x) >> 5;
    int lane = threadIdx.x & 31;
    if (node >= NN) return;

    int beg = g_rowptr[node];
    int end = g_rowptr[node + 1];

    float m = -FLT_MAX;
    int p = beg;
    // 2-way unroll for MLP
    for (; p + 2 <= end; p += 2) {
        int s0 = g_adj[p];
        int s1 = g_adj[p + 1];
        float v0 = hin[s0 * CC + lane];
        float v1 = hin[s1 * CC + lane];
        m = fmaxf(m, fmaxf(v0, v1));
    }
    if (p < end) {
        int s0 = g_adj[p];
        m = fmaxf(m, hin[s0 * CC + lane]);
    }
    if (beg == end) m = 0.0f;

    float x_l = hin[node * CC + lane];

    float acc = sbl[lane];
#pragma unroll
    for (int k = 0; k < CC; k++) {
        float a = __shfl_sync(0xffffffff, m, k);
        float xv = __shfl_sync(0xffffffff, x_l, k);
        acc += a * sWl[k * CC + lane] + xv * sWr[k * CC + lane];
    }

    if (!FINAL) {
        hout[node * CC + lane] = fmaxf(acc, 0.0f);
    } else {
        float mx = acc;
#pragma unroll
        for (int o = 16; o > 0; o >>= 1) mx = fmaxf(mx, __shfl_xor_sync(0xffffffff, mx, o));
        float e = expf(acc - mx);
        float s = e;
#pragma unroll
        for (int o = 16; o > 0; o >>= 1) s += __shfl_xor_sync(0xffffffff, s, o);
        hout[node * CC + lane] = acc - mx - logf(s);
    }
}

extern "C" void kernel_launch(void* const* d_in, const int* in_sizes, int n_in,
                              void* d_out, int out_size) {
    const float* x = (const float*)d_in[0];
    const int* ei = (const int*)d_in[1];
    const float* Wl1 = (const float*)d_in[2];
    const float* bl1 = (const float*)d_in[3];
    const float* Wr1 = (const float*)d_in[4];
    const float* Wl2 = (const float*)d_in[5];
    const float* bl2 = (const float*)d_in[6];
    const float* Wr2 = (const float*)d_in[7];
    const float* Wl3 = (const float*)d_in[8];
    const float* bl3 = (const float*)d_in[9];
    const float* Wr3 = (const float*)d_in[10];
    float* out = (float*)d_out;

    int E = in_sizes[1] / 2;  // 1600000

    const int TB = 256;
    int nblk = (NN + TB - 1) / TB;
    int eblk = (E + TB - 1) / TB;
    int sblk = (NN + SCAN_B - 1) / SCAN_B;  // 98
    int node_blocks = (NN * 32 + TB - 1) / TB;  // warp per node

    // ---- CSR build ----
    zero_cnt<<<nblk, TB>>>();
    hist_dst<<<eblk, TB>>>(ei, E);
    scan_blocks<<<sblk, SCAN_B>>>();
    scan_bsums<<<1, 128>>>(sblk);
    make_rowptr<<<nblk, TB>>>(E);
    csr_scatter<<<eblk, TB>>>(ei, E);

    // ---- fused layers ----
    float* ha;  cudaGetSymbolAddress((void**)&ha, g_ha);
    float* hb;  cudaGetSymbolAddress((void**)&hb, g_hb);
    layer1<<<node_blocks, TB>>>(x, Wl1, bl1, Wr1);
    layer23<false><<<node_blocks, TB>>>(ha, hb, Wl2, bl2, Wr2);
    layer23<true><<<node_blocks, TB>>>(hb, out, Wl3, bl3, Wr3);
}